// round 3
// baseline (speedup 1.0000x reference)
#include <cuda_runtime.h>
#include <cstdint>
#include <cstddef>

#define NN 50000
#define EE 800000
#define CC 128

// ---------------- scratch (device globals; no allocation allowed) ----------------
__device__ float g_aggc[NN * CC];   // cos-branch aggregation (reused layer 0 and 1)
__device__ float g_agge[NN * CC];   // eud-branch aggregation (reused layer 0 and 1)
__device__ float g_deg[NN];         // in-degree (per row index), computed once
__device__ float g_xwr[NN * CC];    // x @ Wr0 + bl0 (shared by both branches)
__device__ float g_x1[NN * CC];     // layer-1 cos output
__device__ float g_x2[NN * CC];     // layer-1 eud output

// ---------------- helpers ----------------
__device__ __forceinline__ float wsum(float v) {
#pragma unroll
    for (int o = 16; o; o >>= 1) v += __shfl_xor_sync(0xFFFFFFFFu, v, o);
    return v;
}

__device__ __forceinline__ void red_v4(float* p, float a, float b, float c, float d) {
    asm volatile("red.global.add.v4.f32 [%0], {%1,%2,%3,%4};"
                 :: "l"(__cvta_generic_to_global(p)), "f"(a), "f"(b), "f"(c), "f"(d)
                 : "memory");
}

// ---------------- zeroing ----------------
__global__ void zero_kernel(int zero_deg) {
    size_t total = (size_t)NN * CC;
    size_t stride = (size_t)gridDim.x * blockDim.x;
    for (size_t i = (size_t)blockIdx.x * blockDim.x + threadIdx.x; i < total; i += stride) {
        g_aggc[i] = 0.f;
        g_agge[i] = 0.f;
        if (zero_deg && i < NN) g_deg[i] = 0.f;
    }
}

// ---------------- edge pass 1: cos + eud sims over x, fused dual scatter ----------------
__global__ void __launch_bounds__(256) edge_pass1(const float* __restrict__ x,
                                                  const int* __restrict__ row,
                                                  const int* __restrict__ col) {
    int e = blockIdx.x * 8 + (threadIdx.x >> 5);
    if (e >= EE) return;
    int lane = threadIdx.x & 31;
    int r = __ldg(row + e), c = __ldg(col + e);
    float4 a = *(const float4*)(x + (size_t)r * CC + lane * 4);
    float4 b = *(const float4*)(x + (size_t)c * CC + lane * 4);
    float dot = a.x * b.x + a.y * b.y + a.z * b.z + a.w * b.w;
    float na  = a.x * a.x + a.y * a.y + a.z * a.z + a.w * a.w;
    float nb  = b.x * b.x + b.y * b.y + b.z * b.z + b.w * b.w;
    float dx = a.x - b.x + 1e-6f, dy = a.y - b.y + 1e-6f;
    float dz = a.z - b.z + 1e-6f, dw = a.w - b.w + 1e-6f;
    float ee = dx * dx + dy * dy + dz * dz + dw * dw;
    dot = wsum(dot); na = wsum(na); nb = wsum(nb); ee = wsum(ee);
    float ecos = dot / fmaxf(sqrtf(na) * sqrtf(nb), 1e-8f);
    float eeud = sqrtf(ee);
    size_t off = (size_t)r * CC + lane * 4;
    red_v4(g_aggc + off, ecos * b.x, ecos * b.y, ecos * b.z, ecos * b.w);
    red_v4(g_agge + off, eeud * b.x, eeud * b.y, eeud * b.z, eeud * b.w);
    if (lane == 0) atomicAdd(&g_deg[r], 1.0f);
}

// ---------------- edge pass 2: layer-1 sims over x3 (cos) and x4 (eud) ----------------
__global__ void __launch_bounds__(256) edge_pass2(const float* __restrict__ x3,
                                                  const float* __restrict__ x4,
                                                  const int* __restrict__ row,
                                                  const int* __restrict__ col) {
    int e = blockIdx.x * 8 + (threadIdx.x >> 5);
    if (e >= EE) return;
    int lane = threadIdx.x & 31;
    int r = __ldg(row + e), c = __ldg(col + e);
    size_t ro = (size_t)r * CC + lane * 4;
    size_t co = (size_t)c * CC + lane * 4;
    float4 a3 = *(const float4*)(x3 + ro);
    float4 b3 = *(const float4*)(x3 + co);
    float4 a4 = *(const float4*)(x4 + ro);
    float4 b4 = *(const float4*)(x4 + co);
    // cosine on x3
    float dot = a3.x * b3.x + a3.y * b3.y + a3.z * b3.z + a3.w * b3.w;
    float na  = a3.x * a3.x + a3.y * a3.y + a3.z * a3.z + a3.w * a3.w;
    float nb  = b3.x * b3.x + b3.y * b3.y + b3.z * b3.z + b3.w * b3.w;
    // euclidean on x4
    float dx = a4.x - b4.x + 1e-6f, dy = a4.y - b4.y + 1e-6f;
    float dz = a4.z - b4.z + 1e-6f, dw = a4.w - b4.w + 1e-6f;
    float ee = dx * dx + dy * dy + dz * dz + dw * dw;
    dot = wsum(dot); na = wsum(na); nb = wsum(nb); ee = wsum(ee);
    float ecos = dot / fmaxf(sqrtf(na) * sqrtf(nb), 1e-8f);
    float eeud = sqrtf(ee);
    red_v4(g_aggc + ro, ecos * b3.x, ecos * b3.y, ecos * b3.z, ecos * b3.w);
    red_v4(g_agge + ro, eeud * b4.x, eeud * b4.y, eeud * b4.z, eeud * b4.w);
}

// ---------------- fused SGEMM: O = f( [A/deg]@B (+ A2@B2) (+ bias) (+ Cadd) ) --------
// Fixed K=N=128 per pass. Block tile 128x128, 256 threads, 8x8 per thread.
template<bool DEG, bool DUAL, bool BIAS, bool CADD, bool RELU>
__global__ void __launch_bounds__(256) gemm_k(
    const float* __restrict__ A, const float* __restrict__ A2,
    const float* __restrict__ B, const float* __restrict__ B2,
    const float* __restrict__ bias, const float* __restrict__ Cadd,
    float* __restrict__ O, int M)
{
    __shared__ float As[16][128];
    __shared__ float Bs[16][128];
    int tid = threadIdx.x;
    int bm = blockIdx.x * 128;
    int tx = tid & 15, ty = tid >> 4;
    float acc[8][8];
#pragma unroll
    for (int i = 0; i < 8; i++)
#pragma unroll
        for (int j = 0; j < 8; j++) acc[i][j] = 0.f;

    const int npass = DUAL ? 2 : 1;
    for (int pass = 0; pass < npass; ++pass) {
        const float* Ap = (DUAL && pass) ? A2 : A;
        const float* Bp = (DUAL && pass) ? B2 : B;
        const bool scale = DEG && (pass == 0);
        for (int kt = 0; kt < 128; kt += 16) {
            __syncthreads();
            // A tile: rows 0..127, k cols kt..kt+15, stored transposed As[k][m]
            {
                int r0 = tid >> 2;
                int kc = (tid & 3) * 4;
#pragma unroll
                for (int h = 0; h < 2; ++h) {
                    int r = r0 + h * 64;
                    int gr = bm + r;
                    float4 v = make_float4(0.f, 0.f, 0.f, 0.f);
                    if (gr < M) {
                        v = *(const float4*)(Ap + (size_t)gr * 128 + kt + kc);
                        if (scale) {
                            float s = 1.0f / fmaxf(g_deg[gr], 1.0f);
                            v.x *= s; v.y *= s; v.z *= s; v.w *= s;
                        }
                    }
                    As[kc + 0][r] = v.x; As[kc + 1][r] = v.y;
                    As[kc + 2][r] = v.z; As[kc + 3][r] = v.w;
                }
            }
            // B tile: rows kt..kt+15, all 128 cols
            {
                int br = tid >> 4;
                int bc = (tid & 15) * 8;
                const float4* src = (const float4*)(Bp + (size_t)(kt + br) * 128 + bc);
                *(float4*)&Bs[br][bc]     = src[0];
                *(float4*)&Bs[br][bc + 4] = src[1];
            }
            __syncthreads();
#pragma unroll
            for (int k = 0; k < 16; ++k) {
                float a[8], b[8];
                float4 t;
                t = *(const float4*)&As[k][ty * 8];     a[0]=t.x; a[1]=t.y; a[2]=t.z; a[3]=t.w;
                t = *(const float4*)&As[k][ty * 8 + 4]; a[4]=t.x; a[5]=t.y; a[6]=t.z; a[7]=t.w;
                t = *(const float4*)&Bs[k][tx * 8];     b[0]=t.x; b[1]=t.y; b[2]=t.z; b[3]=t.w;
                t = *(const float4*)&Bs[k][tx * 8 + 4]; b[4]=t.x; b[5]=t.y; b[6]=t.z; b[7]=t.w;
#pragma unroll
                for (int i = 0; i < 8; i++)
#pragma unroll
                    for (int j = 0; j < 8; j++) acc[i][j] += a[i] * b[j];
            }
        }
    }
    // epilogue
#pragma unroll
    for (int i = 0; i < 8; i++) {
        int gr = bm + ty * 8 + i;
        if (gr >= M) break;
        int gc = tx * 8;
#pragma unroll
        for (int j4 = 0; j4 < 8; j4 += 4) {
            float4 v;
            v.x = acc[i][j4 + 0]; v.y = acc[i][j4 + 1];
            v.z = acc[i][j4 + 2]; v.w = acc[i][j4 + 3];
            if (BIAS) {
                v.x += bias[gc + j4 + 0]; v.y += bias[gc + j4 + 1];
                v.z += bias[gc + j4 + 2]; v.w += bias[gc + j4 + 3];
            }
            if (CADD) {
                float4 cv = *(const float4*)(Cadd + (size_t)gr * 128 + gc + j4);
                v.x += cv.x; v.y += cv.y; v.z += cv.z; v.w += cv.w;
            }
            if (RELU) {
                v.x = fmaxf(v.x, 0.f); v.y = fmaxf(v.y, 0.f);
                v.z = fmaxf(v.z, 0.f); v.w = fmaxf(v.w, 0.f);
            }
            *(float4*)(O + (size_t)gr * 128 + gc + j4) = v;
        }
    }
}

// ---------------- attention pooling: one warp per node ----------------
__global__ void __launch_bounds__(128) att_k(const float* __restrict__ x1,
                                             const float* __restrict__ x2,
                                             const float* __restrict__ x3,
                                             const float* __restrict__ x4,
                                             const float* __restrict__ attW1,
                                             const float* __restrict__ attb1,
                                             const float* __restrict__ attW2,
                                             float* __restrict__ emb)
{
    __shared__ float W[128 * 64];
    __shared__ float b1s[64], w2s[64];
    __shared__ float zsh[4][4][128];   // [warp][branch][feature]
    int tid = threadIdx.x, lane = tid & 31, wid = tid >> 5;
    for (int i = tid; i < 128 * 64; i += 128) W[i] = attW1[i];
    if (tid < 64) { b1s[tid] = attb1[tid]; w2s[tid] = attW2[tid]; }
    __syncthreads();

    int node = blockIdx.x * 4 + wid;
    if (node >= NN) return;
    size_t base = (size_t)node * 128;
    *(float4*)&zsh[wid][0][lane * 4] = *(const float4*)(x1 + base + lane * 4);
    *(float4*)&zsh[wid][1][lane * 4] = *(const float4*)(x2 + base + lane * 4);
    *(float4*)&zsh[wid][2][lane * 4] = *(const float4*)(x3 + base + lane * 4);
    *(float4*)&zsh[wid][3][lane * 4] = *(const float4*)(x4 + base + lane * 4);
    __syncwarp();

    float wlog[4];
#pragma unroll
    for (int b = 0; b < 4; b++) {
        float acc1 = 0.f, acc2 = 0.f;
#pragma unroll
        for (int k4 = 0; k4 < 32; k4++) {
            float4 z = *(const float4*)&zsh[wid][b][k4 * 4];
            int k = k4 * 4;
            acc1 += z.x * W[(k + 0) * 64 + lane] + z.y * W[(k + 1) * 64 + lane]
                  + z.z * W[(k + 2) * 64 + lane] + z.w * W[(k + 3) * 64 + lane];
            acc2 += z.x * W[(k + 0) * 64 + lane + 32] + z.y * W[(k + 1) * 64 + lane + 32]
                  + z.z * W[(k + 2) * 64 + lane + 32] + z.w * W[(k + 3) * 64 + lane + 32];
        }
        float h = tanhf(acc1 + b1s[lane]) * w2s[lane]
                + tanhf(acc2 + b1s[lane + 32]) * w2s[lane + 32];
        wlog[b] = wsum(h);
    }
    float m = fmaxf(fmaxf(wlog[0], wlog[1]), fmaxf(wlog[2], wlog[3]));
    float e0 = expf(wlog[0] - m), e1 = expf(wlog[1] - m);
    float e2 = expf(wlog[2] - m), e3 = expf(wlog[3] - m);
    float inv = 1.0f / (e0 + e1 + e2 + e3);
    float be0 = e0 * inv, be1 = e1 * inv, be2 = e2 * inv, be3 = e3 * inv;

    float4 z0 = *(const float4*)&zsh[wid][0][lane * 4];
    float4 z1 = *(const float4*)&zsh[wid][1][lane * 4];
    float4 z2 = *(const float4*)&zsh[wid][2][lane * 4];
    float4 z3 = *(const float4*)&zsh[wid][3][lane * 4];
    float4 o;
    o.x = be0 * z0.x + be1 * z1.x + be2 * z2.x + be3 * z3.x;
    o.y = be0 * z0.y + be1 * z1.y + be2 * z2.y + be3 * z3.y;
    o.z = be0 * z0.z + be1 * z1.z + be2 * z2.z + be3 * z3.z;
    o.w = be0 * z0.w + be1 * z1.w + be2 * z2.w + be3 * z3.w;
    *(float4*)(emb + base + lane * 4) = o;
}

// ---------------- launch ----------------
extern "C" void kernel_launch(void* const* d_in, const int* in_sizes, int n_in,
                              void* d_out, int out_size)
{
    const float* x   = (const float*)d_in[0];
    const int*   row = (const int*)d_in[1];
    const int*   col = (const int*)d_in[2];
    const float* Wl0 = (const float*)d_in[3];
    const float* bl0 = (const float*)d_in[4];
    const float* Wr0 = (const float*)d_in[5];
    const float* Wl1 = (const float*)d_in[6];
    const float* bl1 = (const float*)d_in[7];
    const float* Wr1 = (const float*)d_in[8];
    const float* aW1 = (const float*)d_in[9];
    const float* ab1 = (const float*)d_in[10];
    const float* aW2 = (const float*)d_in[11];

    float* out = (float*)d_out;
    float* x3  = out + (size_t)NN * CC;       // output slot 2
    float* x4  = out + 2 * (size_t)NN * CC;   // output slot 3

    float *aggc, *agge, *xwr, *x1, *x2;
    cudaGetSymbolAddress((void**)&aggc, g_aggc);
    cudaGetSymbolAddress((void**)&agge, g_agge);
    cudaGetSymbolAddress((void**)&xwr,  g_xwr);
    cudaGetSymbolAddress((void**)&x1,   g_x1);
    cudaGetSymbolAddress((void**)&x2,   g_x2);

    const int gm = (NN + 127) / 128;
    const int ge = (EE + 7) / 8;

    // Layer 0
    zero_kernel<<<4096, 256>>>(1);
    edge_pass1<<<ge, 256>>>(x, row, col);
    // xwr = x @ Wr0 + bl0 (shared by both branches)
    gemm_k<false, false, true, false, false><<<gm, 256>>>(x, nullptr, Wr0, nullptr, bl0, nullptr, xwr, NN);
    // x3 = relu(aggc/deg @ Wl0 + xwr)
    gemm_k<true, false, false, true, true><<<gm, 256>>>(aggc, nullptr, Wl0, nullptr, nullptr, xwr, x3, NN);
    // x4 = relu(agge/deg @ Wl0 + xwr)
    gemm_k<true, false, false, true, true><<<gm, 256>>>(agge, nullptr, Wl0, nullptr, nullptr, xwr, x4, NN);

    // Layer 1
    zero_kernel<<<4096, 256>>>(0);
    edge_pass2<<<ge, 256>>>(x3, x4, row, col);
    // x1 = aggc/deg @ Wl1 + x3 @ Wr1 + bl1
    gemm_k<true, true, true, false, false><<<gm, 256>>>(aggc, x3, Wl1, Wr1, bl1, nullptr, x1, NN);
    // x2 = agge/deg @ Wl1 + x4 @ Wr1 + bl1
    gemm_k<true, true, true, false, false><<<gm, 256>>>(agge, x4, Wl1, Wr1, bl1, nullptr, x2, NN);

    // Attention pooling -> emb
    att_k<<<(NN + 3) / 4, 128>>>(x1, x2, x3, x4, aW1, ab1, aW2, out);
}

// round 5
// speedup vs baseline: 1.2314x; 1.2314x over previous
#include <cuda_runtime.h>
#include <cuda_bf16.h>
#include <cstdint>
#include <cstddef>

#define NN 50000
#define EE 800000
#define CC 128

// ---------------- scratch (device globals) ----------------
__device__ float g_aggc[NN * CC];
__device__ float g_agge[NN * CC];
__device__ float g_deg[NN];
__device__ float g_x1[NN * CC];
__device__ float g_x2[NN * CC];

// ---------------- helpers ----------------
__device__ __forceinline__ float wsum(float v) {
#pragma unroll
    for (int o = 16; o; o >>= 1) v += __shfl_xor_sync(0xFFFFFFFFu, v, o);
    return v;
}
__device__ __forceinline__ void red_v4(float* p, float a, float b, float c, float d) {
    asm volatile("red.global.add.v4.f32 [%0], {%1,%2,%3,%4};"
                 :: "l"(__cvta_generic_to_global(p)), "f"(a), "f"(b), "f"(c), "f"(d)
                 : "memory");
}
__device__ __forceinline__ uint32_t smem_u32(const void* p) {
    uint32_t a;
    asm("{ .reg .u64 t; cvta.to.shared.u64 t, %1; cvt.u32.u64 %0, t; }" : "=r"(a) : "l"(p));
    return a;
}

// pack two floats -> bf16x2 (x in low half), and residual pair in 'lo'
__device__ __forceinline__ uint32_t pack2(float x, float y, uint32_t& lo) {
    uint32_t h;
    asm("cvt.rn.bf16x2.f32 %0, %1, %2;" : "=r"(h) : "f"(y), "f"(x));
    float hx = __uint_as_float(h << 16);
    float hy = __uint_as_float(h & 0xFFFF0000u);
    float rx = x - hx, ry = y - hy;
    asm("cvt.rn.bf16x2.f32 %0, %1, %2;" : "=r"(lo) : "f"(ry), "f"(rx));
    return h;
}

__device__ __forceinline__ void ldsm4(uint32_t (&r)[4], uint32_t addr) {
    asm volatile("ldmatrix.sync.aligned.m8n8.x4.shared.b16 {%0,%1,%2,%3}, [%4];"
                 : "=r"(r[0]), "=r"(r[1]), "=r"(r[2]), "=r"(r[3]) : "r"(addr));
}

__device__ __forceinline__ void mma_bf16(float (&d)[4], const uint32_t (&a)[4],
                                         uint32_t b0, uint32_t b1) {
    asm volatile("mma.sync.aligned.m16n8k16.row.col.f32.bf16.bf16.f32 "
                 "{%0,%1,%2,%3}, {%4,%5,%6,%7}, {%8,%9}, {%0,%1,%2,%3};"
                 : "+f"(d[0]), "+f"(d[1]), "+f"(d[2]), "+f"(d[3])
                 : "r"(a[0]), "r"(a[1]), "r"(a[2]), "r"(a[3]), "r"(b0), "r"(b1));
}

// ---------------- smem layout (bytes) ----------------
#define OFF_BIAS 0
#define OFF_AHI  1024
#define OFF_ALO  (OFF_AHI + 32768)
#define OFF_BHI  (OFF_ALO + 32768)
#define OFF_BLO  (OFF_BHI + 32768)
#define SMEM_BYTES (OFF_BLO + 32768)

// swizzled byte offset within a [128 rows][128 bf16] tile: 16B chunk c of row r
__device__ __forceinline__ uint32_t tile_off(int row, int chunk) {
    return (uint32_t)(row * 256 + (((chunk ^ (row & 7)) & 15) << 4));
}

// A tile: rows bm..bm+127 of src [*, 128] fp32 -> hi/lo bf16, optional 1/deg scale
__device__ __forceinline__ void convA(char* sm, const float* __restrict__ src,
                                      int bm, const float* __restrict__ deg, int tid) {
    int r = tid >> 1, half = tid & 1;
    int gr = bm + r;
    bool valid = gr < NN;
    float sc = 1.0f;
    if (deg != nullptr && valid) sc = 1.0f / fmaxf(deg[gr], 1.0f);
    const float4* s4 = (const float4*)(src + (size_t)(valid ? gr : 0) * CC + half * 64);
#pragma unroll
    for (int i = 0; i < 8; ++i) {
        float4 v0 = make_float4(0.f, 0.f, 0.f, 0.f), v1 = v0;
        if (valid) { v0 = s4[2 * i]; v1 = s4[2 * i + 1]; }
        v0.x *= sc; v0.y *= sc; v0.z *= sc; v0.w *= sc;
        v1.x *= sc; v1.y *= sc; v1.z *= sc; v1.w *= sc;
        uint4 H, L;
        H.x = pack2(v0.x, v0.y, L.x);
        H.y = pack2(v0.z, v0.w, L.y);
        H.z = pack2(v1.x, v1.y, L.z);
        H.w = pack2(v1.z, v1.w, L.w);
        uint32_t off = tile_off(r, half * 8 + i);
        *(uint4*)(sm + OFF_AHI + off) = H;
        *(uint4*)(sm + OFF_ALO + off) = L;
    }
}

// B tile: Bmma[n][k] = W[k][n]  (W row-major [128][128])
__device__ __forceinline__ void convB(char* sm, const float* __restrict__ W, int tid) {
    int n = tid >> 1, half = tid & 1;
#pragma unroll
    for (int i = 0; i < 8; ++i) {
        int k = (half * 8 + i) * 8;
        float v[8];
#pragma unroll
        for (int j = 0; j < 8; ++j) v[j] = __ldg(W + (size_t)(k + j) * CC + n);
        uint4 H, L;
        H.x = pack2(v[0], v[1], L.x);
        H.y = pack2(v[2], v[3], L.y);
        H.z = pack2(v[4], v[5], L.z);
        H.w = pack2(v[6], v[7], L.w);
        uint32_t off = tile_off(n, half * 8 + i);
        *(uint4*)(sm + OFF_BHI + off) = H;
        *(uint4*)(sm + OFF_BLO + off) = L;
    }
}

// one full 128x128x128 GEMM accumulate (3-term hi/lo split) for this warp's 32x64 tile
__device__ __forceinline__ void warp_pass(uint32_t smb, int wm, int wn, int lane,
                                          float (&acc)[16][4]) {
    int quad = lane >> 3, l7 = lane & 7;
    uint32_t arb[2]; int ar7[2];
    int acoff = quad >> 1;
#pragma unroll
    for (int mt = 0; mt < 2; ++mt) {
        int row = wm + mt * 16 + (quad & 1) * 8 + l7;
        arb[mt] = (uint32_t)(row * 256); ar7[mt] = row & 7;
    }
    uint32_t brb[4]; int br7[4];
    int bcoff = quad & 1;
#pragma unroll
    for (int j = 0; j < 4; ++j) {
        int row = wn + j * 16 + (quad >> 1) * 8 + l7;
        brb[j] = (uint32_t)(row * 256); br7[j] = row & 7;
    }
#pragma unroll
    for (int term = 0; term < 3; ++term) {
        uint32_t aBase = smb + ((term == 2) ? OFF_ALO : OFF_AHI);
        uint32_t bBase = smb + ((term == 1) ? OFF_BLO : OFF_BHI);
#pragma unroll
        for (int ks = 0; ks < 8; ++ks) {
            uint32_t a[2][4];
#pragma unroll
            for (int mt = 0; mt < 2; ++mt)
                ldsm4(a[mt], aBase + arb[mt] + ((((2 * ks + acoff) ^ ar7[mt]) & 15) << 4));
            uint32_t b[4][4];
#pragma unroll
            for (int j = 0; j < 4; ++j)
                ldsm4(b[j], bBase + brb[j] + ((((2 * ks + bcoff) ^ br7[j]) & 15) << 4));
#pragma unroll
            for (int mt = 0; mt < 2; ++mt)
#pragma unroll
                for (int nt = 0; nt < 8; ++nt)
                    mma_bf16(acc[mt * 8 + nt], a[mt],
                             b[nt >> 1][(nt & 1) * 2], b[nt >> 1][(nt & 1) * 2 + 1]);
        }
    }
}

// ---------------- fused dual GEMM ----------------
// L0: Dc = x@Wr0 + aggc/deg@Wl0 ; De = x@Wr0 + agge/deg@Wl0 ; O = relu(D + bias)
// L1: Dc = x3@Wr1 + aggc/deg@Wl1 ; De = x4@Wr1 + agge/deg@Wl1 ; O = D + bias
template<bool L0>
__global__ void __launch_bounds__(256, 1) fused_gemm(
    const float* __restrict__ A0, const float* __restrict__ A1,
    const float* __restrict__ Wl, const float* __restrict__ Wr,
    const float* __restrict__ bias,
    float* __restrict__ O1, float* __restrict__ O2)
{
    extern __shared__ char sm[];
    const int tid = threadIdx.x, lane = tid & 31, wid = tid >> 5;
    const int bm = blockIdx.x * 128;
    uint32_t smb = smem_u32(sm);
    float* sbias = (float*)(sm + OFF_BIAS);
    if (tid < 128) sbias[tid] = bias[tid];

    float accC[16][4], accE[16][4];
#pragma unroll
    for (int i = 0; i < 16; ++i)
#pragma unroll
        for (int j = 0; j < 4; ++j) { accC[i][j] = 0.f; accE[i][j] = 0.f; }

    const int wm = (wid & 3) * 32, wn = (wid >> 2) * 64;

    // pass 1: B=Wr, A=A0 -> accC
    convB(sm, Wr, tid);
    convA(sm, A0, bm, nullptr, tid);
    __syncthreads();
    warp_pass(smb, wm, wn, lane, accC);
    if (L0) {
#pragma unroll
        for (int i = 0; i < 16; ++i)
#pragma unroll
            for (int j = 0; j < 4; ++j) accE[i][j] = accC[i][j];
    } else {
        __syncthreads();
        convA(sm, A1, bm, nullptr, tid);
        __syncthreads();
        warp_pass(smb, wm, wn, lane, accE);
    }

    // pass 2: B=Wl, A=aggc/deg -> accC
    __syncthreads();
    convB(sm, Wl, tid);
    convA(sm, g_aggc, bm, g_deg, tid);
    __syncthreads();
    warp_pass(smb, wm, wn, lane, accC);

    // pass 3: A=agge/deg -> accE
    __syncthreads();
    convA(sm, g_agge, bm, g_deg, tid);
    __syncthreads();
    warp_pass(smb, wm, wn, lane, accE);

    // epilogue
    int g = lane >> 2, tg = lane & 3;
#pragma unroll
    for (int mt = 0; mt < 2; ++mt) {
        int m0 = bm + wm + mt * 16 + g;
#pragma unroll
        for (int nt = 0; nt < 8; ++nt) {
            int cgl = wn + nt * 8 + tg * 2;
            float b0 = sbias[cgl], b1 = sbias[cgl + 1];
            int idx = mt * 8 + nt;
            if (m0 < NN) {
                float2 v, w;
                v.x = accC[idx][0] + b0; v.y = accC[idx][1] + b1;
                w.x = accE[idx][0] + b0; w.y = accE[idx][1] + b1;
                if (L0) {
                    v.x = fmaxf(v.x, 0.f); v.y = fmaxf(v.y, 0.f);
                    w.x = fmaxf(w.x, 0.f); w.y = fmaxf(w.y, 0.f);
                }
                *(float2*)(O1 + (size_t)m0 * CC + cgl) = v;
                *(float2*)(O2 + (size_t)m0 * CC + cgl) = w;
            }
            if (m0 + 8 < NN) {
                float2 v, w;
                v.x = accC[idx][2] + b0; v.y = accC[idx][3] + b1;
                w.x = accE[idx][2] + b0; w.y = accE[idx][3] + b1;
                if (L0) {
                    v.x = fmaxf(v.x, 0.f); v.y = fmaxf(v.y, 0.f);
                    w.x = fmaxf(w.x, 0.f); w.y = fmaxf(w.y, 0.f);
                }
                *(float2*)(O1 + (size_t)(m0 + 8) * CC + cgl) = v;
                *(float2*)(O2 + (size_t)(m0 + 8) * CC + cgl) = w;
            }
        }
    }
}

// ---------------- edge pass 1 ----------------
__global__ void __launch_bounds__(256) edge_pass1(const float* __restrict__ x,
                                                  const int* __restrict__ row,
                                                  const int* __restrict__ col) {
    int e = blockIdx.x * 8 + (threadIdx.x >> 5);
    if (e >= EE) return;
    int lane = threadIdx.x & 31;
    int r = __ldg(row + e), c = __ldg(col + e);
    float4 a = *(const float4*)(x + (size_t)r * CC + lane * 4);
    float4 b = *(const float4*)(x + (size_t)c * CC + lane * 4);
    float dot = a.x * b.x + a.y * b.y + a.z * b.z + a.w * b.w;
    float na  = a.x * a.x + a.y * a.y + a.z * a.z + a.w * a.w;
    float nb  = b.x * b.x + b.y * b.y + b.z * b.z + b.w * b.w;
    float dx = a.x - b.x + 1e-6f, dy = a.y - b.y + 1e-6f;
    float dz = a.z - b.z + 1e-6f, dw = a.w - b.w + 1e-6f;
    float ee = dx * dx + dy * dy + dz * dz + dw * dw;
    dot = wsum(dot); na = wsum(na); nb = wsum(nb); ee = wsum(ee);
    float ecos = dot / fmaxf(sqrtf(na) * sqrtf(nb), 1e-8f);
    float eeud = sqrtf(ee);
    size_t off = (size_t)r * CC + lane * 4;
    red_v4(g_aggc + off, ecos * b.x, ecos * b.y, ecos * b.z, ecos * b.w);
    red_v4(g_agge + off, eeud * b.x, eeud * b.y, eeud * b.z, eeud * b.w);
    if (lane == 0) atomicAdd(&g_deg[r], 1.0f);
}

// ---------------- edge pass 2 ----------------
__global__ void __launch_bounds__(256) edge_pass2(const float* __restrict__ x3,
                                                  const float* __restrict__ x4,
                                                  const int* __restrict__ row,
                                                  const int* __restrict__ col) {
    int e = blockIdx.x * 8 + (threadIdx.x >> 5);
    if (e >= EE) return;
    int lane = threadIdx.x & 31;
    int r = __ldg(row + e), c = __ldg(col + e);
    size_t ro = (size_t)r * CC + lane * 4;
    size_t co = (size_t)c * CC + lane * 4;
    float4 a3 = *(const float4*)(x3 + ro);
    float4 b3 = *(const float4*)(x3 + co);
    float4 a4 = *(const float4*)(x4 + ro);
    float4 b4 = *(const float4*)(x4 + co);
    float dot = a3.x * b3.x + a3.y * b3.y + a3.z * b3.z + a3.w * b3.w;
    float na  = a3.x * a3.x + a3.y * a3.y + a3.z * a3.z + a3.w * a3.w;
    float nb  = b3.x * b3.x + b3.y * b3.y + b3.z * b3.z + b3.w * b3.w;
    float dx = a4.x - b4.x + 1e-6f, dy = a4.y - b4.y + 1e-6f;
    float dz = a4.z - b4.z + 1e-6f, dw = a4.w - b4.w + 1e-6f;
    float ee = dx * dx + dy * dy + dz * dz + dw * dw;
    dot = wsum(dot); na = wsum(na); nb = wsum(nb); ee = wsum(ee);
    float ecos = dot / fmaxf(sqrtf(na) * sqrtf(nb), 1e-8f);
    float eeud = sqrtf(ee);
    red_v4(g_aggc + ro, ecos * b3.x, ecos * b3.y, ecos * b3.z, ecos * b3.w);
    red_v4(g_agge + ro, eeud * b4.x, eeud * b4.y, eeud * b4.z, eeud * b4.w);
}

// ---------------- attention pooling: one warp per node, 6 warps/block ----------------
__global__ void __launch_bounds__(192) att_k(const float* __restrict__ x1,
                                             const float* __restrict__ x2,
                                             const float* __restrict__ x3,
                                             const float* __restrict__ x4,
                                             const float* __restrict__ attW1,
                                             const float* __restrict__ attb1,
                                             const float* __restrict__ attW2,
                                             float* __restrict__ emb)
{
    __shared__ float W[128 * 64];
    __shared__ float b1s[64], w2s[64];
    __shared__ float zsh[6][4][128];
    int tid = threadIdx.x, lane = tid & 31, wid = tid >> 5;
    for (int i = tid; i < 128 * 64; i += 192) W[i] = attW1[i];
    if (tid < 64) { b1s[tid] = attb1[tid]; w2s[tid] = attW2[tid]; }
    __syncthreads();

    int node = blockIdx.x * 6 + wid;
    if (node >= NN) return;
    size_t base = (size_t)node * 128;
    *(float4*)&zsh[wid][0][lane * 4] = *(const float4*)(x1 + base + lane * 4);
    *(float4*)&zsh[wid][1][lane * 4] = *(const float4*)(x2 + base + lane * 4);
    *(float4*)&zsh[wid][2][lane * 4] = *(const float4*)(x3 + base + lane * 4);
    *(float4*)&zsh[wid][3][lane * 4] = *(const float4*)(x4 + base + lane * 4);
    __syncwarp();

    float wlog[4];
#pragma unroll
    for (int b = 0; b < 4; b++) {
        float acc1 = 0.f, acc2 = 0.f;
#pragma unroll
        for (int k4 = 0; k4 < 32; k4++) {
            float4 z = *(const float4*)&zsh[wid][b][k4 * 4];
            int k = k4 * 4;
            acc1 += z.x * W[(k + 0) * 64 + lane] + z.y * W[(k + 1) * 64 + lane]
                  + z.z * W[(k + 2) * 64 + lane] + z.w * W[(k + 3) * 64 + lane];
            acc2 += z.x * W[(k + 0) * 64 + lane + 32] + z.y * W[(k + 1) * 64 + lane + 32]
                  + z.z * W[(k + 2) * 64 + lane + 32] + z.w * W[(k + 3) * 64 + lane + 32];
        }
        float h = tanhf(acc1 + b1s[lane]) * w2s[lane]
                + tanhf(acc2 + b1s[lane + 32]) * w2s[lane + 32];
        wlog[b] = wsum(h);
    }
    float m = fmaxf(fmaxf(wlog[0], wlog[1]), fmaxf(wlog[2], wlog[3]));
    float e0 = expf(wlog[0] - m), e1 = expf(wlog[1] - m);
    float e2 = expf(wlog[2] - m), e3 = expf(wlog[3] - m);
    float inv = 1.0f / (e0 + e1 + e2 + e3);
    float be0 = e0 * inv, be1 = e1 * inv, be2 = e2 * inv, be3 = e3 * inv;

    float4 z0 = *(const float4*)&zsh[wid][0][lane * 4];
    float4 z1 = *(const float4*)&zsh[wid][1][lane * 4];
    float4 z2 = *(const float4*)&zsh[wid][2][lane * 4];
    float4 z3 = *(const float4*)&zsh[wid][3][lane * 4];
    float4 o;
    o.x = be0 * z0.x + be1 * z1.x + be2 * z2.x + be3 * z3.x;
    o.y = be0 * z0.y + be1 * z1.y + be2 * z2.y + be3 * z3.y;
    o.z = be0 * z0.z + be1 * z1.z + be2 * z2.z + be3 * z3.z;
    o.w = be0 * z0.w + be1 * z1.w + be2 * z2.w + be3 * z3.w;
    *(float4*)(emb + base + lane * 4) = o;
}

// ---------------- launch ----------------
extern "C" void kernel_launch(void* const* d_in, const int* in_sizes, int n_in,
                              void* d_out, int out_size)
{
    const float* x   = (const float*)d_in[0];
    const int*   row = (const int*)d_in[1];
    const int*   col = (const int*)d_in[2];
    const float* Wl0 = (const float*)d_in[3];
    const float* bl0 = (const float*)d_in[4];
    const float* Wr0 = (const float*)d_in[5];
    const float* Wl1 = (const float*)d_in[6];
    const float* bl1 = (const float*)d_in[7];
    const float* Wr1 = (const float*)d_in[8];
    const float* aW1 = (const float*)d_in[9];
    const float* ab1 = (const float*)d_in[10];
    const float* aW2 = (const float*)d_in[11];

    float* out = (float*)d_out;
    float* x3  = out + (size_t)NN * CC;
    float* x4  = out + 2 * (size_t)NN * CC;

    float *aggc, *agge, *deg, *x1, *x2;
    cudaGetSymbolAddress((void**)&aggc, g_aggc);
    cudaGetSymbolAddress((void**)&agge, g_agge);
    cudaGetSymbolAddress((void**)&deg,  g_deg);
    cudaGetSymbolAddress((void**)&x1,   g_x1);
    cudaGetSymbolAddress((void**)&x2,   g_x2);

    cudaFuncSetAttribute(fused_gemm<true>,  cudaFuncAttributeMaxDynamicSharedMemorySize, SMEM_BYTES);
    cudaFuncSetAttribute(fused_gemm<false>, cudaFuncAttributeMaxDynamicSharedMemorySize, SMEM_BYTES);

    const int gm = (NN + 127) / 128;
    const int ge = (EE + 7) / 8;
    const size_t agg_bytes = (size_t)NN * CC * sizeof(float);

    // Layer 0
    cudaMemsetAsync(deg,  0, NN * sizeof(float));
    cudaMemsetAsync(aggc, 0, agg_bytes);
    cudaMemsetAsync(agge, 0, agg_bytes);
    edge_pass1<<<ge, 256>>>(x, row, col);
    fused_gemm<true><<<gm, 256, SMEM_BYTES>>>(x, x, Wl0, Wr0, bl0, x3, x4);

    // Layer 1
    cudaMemsetAsync(aggc, 0, agg_bytes);
    cudaMemsetAsync(agge, 0, agg_bytes);
    edge_pass2<<<ge, 256>>>(x3, x4, row, col);
    fused_gemm<false><<<gm, 256, SMEM_BYTES>>>(x3, x4, Wl1, Wr1, bl1, x1, x2);

    // Attention pooling -> emb
    att_k<<<(NN + 5) / 6, 192>>>(x1, x2, x3, x4, aW1, ab1, aW2, out);
}